// round 1
// baseline (speedup 1.0000x reference)
#include <cuda_runtime.h>

#define NSMP   32768
#define TSTEPS 512
#define HID    64
#define NTHR   128

typedef unsigned long long ull;

// ---- packed f32x2 helpers (FFMA2 is PTX-only; ptxas never emits it from C++) ----
__device__ __forceinline__ ull fma2(ull a, ull b, ull c) {
    ull d;
    asm("fma.rn.f32x2 %0, %1, %2, %3;" : "=l"(d) : "l"(a), "l"(b), "l"(c));
    return d;
}
__device__ __forceinline__ ull pack2(float x) {
    ull d;
    asm("mov.b64 %0, {%1, %1};" : "=l"(d) : "f"(x));
    return d;
}
__device__ __forceinline__ float2 unpack2(ull v) {
    float lo, hi;
    asm("mov.b64 {%0, %1}, %2;" : "=f"(lo), "=f"(hi) : "l"(v));
    return make_float2(lo, hi);
}

__device__ __forceinline__ float lipswish(float x) {
    // 0.909 * x * sigmoid(x)
    float s = __fdividef(1.0f, 1.0f + __expf(-x));
    return 0.909f * x * s;
}

__device__ __forceinline__ float softplus_acc(float x) {
    // stable: max(x,0) + log1p(exp(-|x|)) — only 4 per step, keep accurate
    return fmaxf(x, 0.0f) + log1pf(__expf(-fabsf(x)));
}

// Hidden dense layer 64->64 with lipswish, in-place on h. Fully unrolled so h
// stays register-resident.
__device__ __forceinline__ void dense64(const float* __restrict__ W,
                                        const float* __restrict__ B,
                                        float (&h)[HID]) {
    ull acc[32];
    const ull* bb = reinterpret_cast<const ull*>(B);
#pragma unroll
    for (int j = 0; j < 32; j++) acc[j] = bb[j];
#pragma unroll
    for (int k = 0; k < HID; k++) {
        ull aa = pack2(h[k]);
        const ull* w = reinterpret_cast<const ull*>(W + k * HID);
#pragma unroll
        for (int j = 0; j < 32; j++) acc[j] = fma2(aa, w[j], acc[j]);
    }
#pragma unroll
    for (int j = 0; j < 32; j++) {
        float2 v = unpack2(acc[j]);
        h[2 * j]     = lipswish(v.x);
        h[2 * j + 1] = lipswish(v.y);
    }
}

// Full MLP 4 ->64 ->64 ->64 ->4. W layout: W1[4*64] | W2[64*64] | W3[64*64] | W4[64*4]
// B layout: b1[64] | b2[64] | b3[64] | b4[4]
__device__ __forceinline__ float4 mlp(const float* __restrict__ W,
                                      const float* __restrict__ B,
                                      float4 y) {
    float h[HID];
    // layer 1 (K = 4)
    {
        ull acc[32];
        const ull* bb = reinterpret_cast<const ull*>(B);
#pragma unroll
        for (int j = 0; j < 32; j++) acc[j] = bb[j];
        float in[4] = {y.x, y.y, y.z, y.w};
#pragma unroll
        for (int k = 0; k < 4; k++) {
            ull aa = pack2(in[k]);
            const ull* w = reinterpret_cast<const ull*>(W + k * HID);
#pragma unroll
            for (int j = 0; j < 32; j++) acc[j] = fma2(aa, w[j], acc[j]);
        }
#pragma unroll
        for (int j = 0; j < 32; j++) {
            float2 v = unpack2(acc[j]);
            h[2 * j]     = lipswish(v.x);
            h[2 * j + 1] = lipswish(v.y);
        }
    }
    dense64(W + 256,        B + 64,  h);
    dense64(W + 256 + 4096, B + 128, h);
    // layer 4 (64 -> 4), linear
    const ull* b4 = reinterpret_cast<const ull*>(B + 192);
    ull o0 = b4[0], o1 = b4[1];
    const float* W4 = W + 256 + 8192;
#pragma unroll
    for (int k = 0; k < HID; k++) {
        ull aa = pack2(h[k]);
        const ull* w = reinterpret_cast<const ull*>(W4 + k * 4);
        o0 = fma2(aa, w[0], o0);
        o1 = fma2(aa, w[1], o1);
    }
    float2 lo = unpack2(o0), hi = unpack2(o1);
    return make_float4(lo.x, lo.y, hi.x, hi.y);
}

struct Params {
    const float* p[19];
    float* out;
};

// Shared layout (floats): sWf[8704] sWg[8704] sBf[196] sBg[196] sdt[511]
#define OFF_WG  8704
#define OFF_BF  17408
#define OFF_BG  17604
#define OFF_DT  17800
#define SMEM_FLOATS 18312
#define SMEM_BYTES  (SMEM_FLOATS * 4)

__global__ __launch_bounds__(NTHR, 3) void sde_kernel(Params P) {
    extern __shared__ float sm[];
    float* sWf = sm;
    float* sWg = sm + OFF_WG;
    float* sBf = sm + OFF_BF;
    float* sBg = sm + OFF_BG;
    float* sdt = sm + OFF_DT;
    const int tid = threadIdx.x;

    // Stage parameters into shared memory.
    // W layout per net: W1 @0 (256), W2 @256 (4096), W3 @4352 (4096), W4 @8448 (256)
    for (int i = tid; i < 256; i += NTHR) {
        sWf[i]        = P.p[3][i];
        sWf[8448 + i] = P.p[9][i];
        sWg[i]        = P.p[11][i];
        sWg[8448 + i] = P.p[17][i];
    }
    for (int i = tid; i < 4096; i += NTHR) {
        sWf[256 + i]  = P.p[5][i];
        sWf[4352 + i] = P.p[7][i];
        sWg[256 + i]  = P.p[13][i];
        sWg[4352 + i] = P.p[15][i];
    }
    for (int i = tid; i < HID; i += NTHR) {
        sBf[i]        = P.p[4][i];
        sBf[64 + i]   = P.p[6][i];
        sBf[128 + i]  = P.p[8][i];
        sBg[i]        = P.p[12][i];
        sBg[64 + i]   = P.p[14][i];
        sBg[128 + i]  = P.p[16][i];
    }
    if (tid < 4) {
        sBf[192 + tid] = P.p[10][tid];
        sBg[192 + tid] = P.p[18][tid];
    }
    for (int i = tid; i < TSTEPS - 1; i += NTHR)
        sdt[i] = P.p[1][i + 1] - P.p[1][i];
    __syncthreads();

    const int n = blockIdx.x * NTHR + tid;
    const float4* y0 = (const float4*)P.p[0];
    const float4* nz = (const float4*)P.p[2];
    float4* out = (float4*)P.out;

    float4 y = y0[n];
    out[n * TSTEPS] = y;  // t = 0

    for (int t = 0; t < TSTEPS - 1; t++) {
        float4 dw = __ldcs(&nz[t * NSMP + n]);  // issue early to hide DRAM latency
        float dt = sdt[t];
        float sq = sqrtf(dt);

        float4 dr = mlp(sWf, sBf, y);  // drift net
        float4 dg = mlp(sWg, sBg, y);  // diffusion net

        float fx = fminf(fmaxf(dr.x, -100.0f), 100.0f);
        float fy = fminf(fmaxf(dr.y, -100.0f), 100.0f);
        float fz = fminf(fmaxf(dr.z, -100.0f), 100.0f);
        float fw = fminf(fmaxf(dr.w, -100.0f), 100.0f);

        float gx = fmaxf(softplus_acc(dg.x), 1e-4f);
        float gy = fmaxf(softplus_acc(dg.y), 1e-4f);
        float gz = fmaxf(softplus_acc(dg.z), 1e-4f);
        float gw = fmaxf(softplus_acc(dg.w), 1e-4f);

        y.x = y.x + fx * dt + gx * sq * dw.x;
        y.y = y.y + fy * dt + gy * sq * dw.y;
        y.z = y.z + fz * dt + gz * sq * dw.z;
        y.w = y.w + fw * dt + gw * sq * dw.w;

        __stcs(&out[n * TSTEPS + t + 1], y);
    }
}

extern "C" void kernel_launch(void* const* d_in, const int* in_sizes, int n_in,
                              void* d_out, int out_size) {
    Params P;
    for (int i = 0; i < 19; i++) P.p[i] = (const float*)d_in[i];
    P.out = (float*)d_out;

    cudaFuncSetAttribute(sde_kernel, cudaFuncAttributeMaxDynamicSharedMemorySize,
                         SMEM_BYTES);
    sde_kernel<<<NSMP / NTHR, NTHR, SMEM_BYTES>>>(P);
}

// round 3
// speedup vs baseline: 1.0082x; 1.0082x over previous
#include <cuda_runtime.h>

#define NSMP   32768
#define TSTEPS 512
#define HID    64
#define NTHR   224
#define NCTA   147

typedef unsigned long long ull;

// ---- packed f32x2 helpers (FFMA2 is PTX-only; ptxas never emits it from C++) ----
__device__ __forceinline__ ull fma2(ull a, ull b, ull c) {
    ull d;
    asm("fma.rn.f32x2 %0, %1, %2, %3;" : "=l"(d) : "l"(a), "l"(b), "l"(c));
    return d;
}
__device__ __forceinline__ ull pack2(float x) {
    ull d;
    asm("mov.b64 %0, {%1, %1};" : "=l"(d) : "f"(x));
    return d;
}
__device__ __forceinline__ float2 unpack2(ull v) {
    float lo, hi;
    asm("mov.b64 {%0, %1}, %2;" : "=f"(lo), "=f"(hi) : "l"(v));
    return make_float2(lo, hi);
}

__device__ __forceinline__ float lipswish(float x) {
    float s = __fdividef(1.0f, 1.0f + __expf(-x));
    return 0.909f * x * s;
}

__device__ __forceinline__ float softplus_acc(float x) {
    return fmaxf(x, 0.0f) + log1pf(__expf(-fabsf(x)));
}

// Hidden dense layer 64->64 with lipswish, in-place on h.
// Weights read as LDS.128 (ulonglong2) — 16 loads + 32 FFMA2 per k.
__device__ __forceinline__ void dense64(const float* __restrict__ W,
                                        const float* __restrict__ B,
                                        float (&h)[HID]) {
    ull acc[32];
    const ulonglong2* bb = reinterpret_cast<const ulonglong2*>(B);
#pragma unroll
    for (int j = 0; j < 16; j++) {
        ulonglong2 b = bb[j];
        acc[2 * j] = b.x;
        acc[2 * j + 1] = b.y;
    }
#pragma unroll
    for (int k = 0; k < HID; k++) {
        ull aa = pack2(h[k]);
        const ulonglong2* w = reinterpret_cast<const ulonglong2*>(W + k * HID);
#pragma unroll
        for (int j = 0; j < 16; j++) {
            ulonglong2 v = w[j];
            acc[2 * j]     = fma2(aa, v.x, acc[2 * j]);
            acc[2 * j + 1] = fma2(aa, v.y, acc[2 * j + 1]);
        }
    }
#pragma unroll
    for (int j = 0; j < 32; j++) {
        float2 v = unpack2(acc[j]);
        h[2 * j]     = lipswish(v.x);
        h[2 * j + 1] = lipswish(v.y);
    }
}

// Full MLP 4 ->64 ->64 ->64 ->4. W layout: W1[4*64] | W2[64*64] | W3[64*64] | W4[64*4]
__device__ __forceinline__ float4 mlp(const float* __restrict__ W,
                                      const float* __restrict__ B,
                                      float4 y) {
    float h[HID];
    // layer 1 (K = 4)
    {
        ull acc[32];
        const ulonglong2* bb = reinterpret_cast<const ulonglong2*>(B);
#pragma unroll
        for (int j = 0; j < 16; j++) {
            ulonglong2 b = bb[j];
            acc[2 * j] = b.x;
            acc[2 * j + 1] = b.y;
        }
        float in[4] = {y.x, y.y, y.z, y.w};
#pragma unroll
        for (int k = 0; k < 4; k++) {
            ull aa = pack2(in[k]);
            const ulonglong2* w = reinterpret_cast<const ulonglong2*>(W + k * HID);
#pragma unroll
            for (int j = 0; j < 16; j++) {
                ulonglong2 v = w[j];
                acc[2 * j]     = fma2(aa, v.x, acc[2 * j]);
                acc[2 * j + 1] = fma2(aa, v.y, acc[2 * j + 1]);
            }
        }
#pragma unroll
        for (int j = 0; j < 32; j++) {
            float2 v = unpack2(acc[j]);
            h[2 * j]     = lipswish(v.x);
            h[2 * j + 1] = lipswish(v.y);
        }
    }
    dense64(W + 256,        B + 64,  h);
    dense64(W + 256 + 4096, B + 128, h);
    // layer 4 (64 -> 4), linear; each row is one LDS.128
    const ulonglong2* b4 = reinterpret_cast<const ulonglong2*>(B + 192);
    ulonglong2 bo = b4[0];
    ull o0 = bo.x, o1 = bo.y;
    const float* W4 = W + 256 + 8192;
#pragma unroll
    for (int k = 0; k < HID; k++) {
        ull aa = pack2(h[k]);
        ulonglong2 v = reinterpret_cast<const ulonglong2*>(W4 + k * 4)[0];
        o0 = fma2(aa, v.x, o0);
        o1 = fma2(aa, v.y, o1);
    }
    float2 lo = unpack2(o0), hi = unpack2(o1);
    return make_float4(lo.x, lo.y, hi.x, hi.y);
}

struct Params {
    const float* p[19];
    float* out;
};

// Shared layout (floats): sWf[8704] sWg[8704] sBf[196] sBg[196] sdt[511] ssq[511]
#define OFF_WG  8704
#define OFF_BF  17408
#define OFF_BG  17604
#define OFF_DT  17800
#define OFF_SQ  18311
#define SMEM_FLOATS 18824
#define SMEM_BYTES  (SMEM_FLOATS * 4)

__global__ __launch_bounds__(NTHR) void sde_kernel(Params P) {
    extern __shared__ float sm[];
    float* sWf = sm;
    float* sWg = sm + OFF_WG;
    float* sBf = sm + OFF_BF;
    float* sBg = sm + OFF_BG;
    float* sdt = sm + OFF_DT;
    float* ssq = sm + OFF_SQ;
    const int tid = threadIdx.x;

    // Stage parameters into shared memory.
    // W layout per net: W1 @0 (256), W2 @256 (4096), W3 @4352 (4096), W4 @8448 (256)
    for (int i = tid; i < 256; i += NTHR) {
        sWf[i]        = P.p[3][i];
        sWf[8448 + i] = P.p[9][i];
        sWg[i]        = P.p[11][i];
        sWg[8448 + i] = P.p[17][i];
    }
    for (int i = tid; i < 4096; i += NTHR) {
        sWf[256 + i]  = P.p[5][i];
        sWf[4352 + i] = P.p[7][i];
        sWg[256 + i]  = P.p[13][i];
        sWg[4352 + i] = P.p[15][i];
    }
    for (int i = tid; i < HID; i += NTHR) {
        sBf[i]        = P.p[4][i];
        sBf[64 + i]   = P.p[6][i];
        sBf[128 + i]  = P.p[8][i];
        sBg[i]        = P.p[12][i];
        sBg[64 + i]   = P.p[14][i];
        sBg[128 + i]  = P.p[16][i];
    }
    if (tid < 4) {
        sBf[192 + tid] = P.p[10][tid];
        sBg[192 + tid] = P.p[18][tid];
    }
    for (int i = tid; i < TSTEPS - 1; i += NTHR) {
        float dt = P.p[1][i + 1] - P.p[1][i];
        sdt[i] = dt;
        ssq[i] = sqrtf(dt);
    }
    __syncthreads();

    const int n = blockIdx.x * NTHR + tid;
    if (n >= NSMP) return;

    const float4* y0 = (const float4*)P.p[0];
    const float4* nz = (const float4*)P.p[2];
    float4* out = (float4*)P.out;

    float4 y = y0[n];
    out[n * TSTEPS] = y;  // t = 0

    for (int t = 0; t < TSTEPS - 1; t++) {
        float4 dw = __ldcs(&nz[t * NSMP + n]);  // issue early to hide DRAM latency
        float dt = sdt[t];
        float sq = ssq[t];

        float4 dr = mlp(sWf, sBf, y);  // drift net
        float4 dg = mlp(sWg, sBg, y);  // diffusion net

        float fx = fminf(fmaxf(dr.x, -100.0f), 100.0f);
        float fy = fminf(fmaxf(dr.y, -100.0f), 100.0f);
        float fz = fminf(fmaxf(dr.z, -100.0f), 100.0f);
        float fw = fminf(fmaxf(dr.w, -100.0f), 100.0f);

        float gx = fmaxf(softplus_acc(dg.x), 1e-4f);
        float gy = fmaxf(softplus_acc(dg.y), 1e-4f);
        float gz = fmaxf(softplus_acc(dg.z), 1e-4f);
        float gw = fmaxf(softplus_acc(dg.w), 1e-4f);

        y.x = y.x + fx * dt + gx * sq * dw.x;
        y.y = y.y + fy * dt + gy * sq * dw.y;
        y.z = y.z + fz * dt + gz * sq * dw.z;
        y.w = y.w + fw * dt + gw * sq * dw.w;

        __stcs(&out[n * TSTEPS + t + 1], y);
    }
}

extern "C" void kernel_launch(void* const* d_in, const int* in_sizes, int n_in,
                              void* d_out, int out_size) {
    Params P;
    for (int i = 0; i < 19; i++) P.p[i] = (const float*)d_in[i];
    P.out = (float*)d_out;

    cudaFuncSetAttribute(sde_kernel, cudaFuncAttributeMaxDynamicSharedMemorySize,
                         SMEM_BYTES);
    sde_kernel<<<NCTA, NTHR, SMEM_BYTES>>>(P);
}